// round 13
// baseline (speedup 1.0000x reference)
#include <cuda_runtime.h>
#include <cuda_fp16.h>
#include <cuda_bf16.h>

// GraphConvDistanceLayer: out[i] = sum_{e: rows[e]==i} Param_W[params[e]] * x[cols[e]]
//                                 + Param_b[b_params[i]]
//
// Inputs (metadata order):
//   d_in[0] = x        float32 [N]      N = 262144
//   d_in[1] = Param_W  float32 [1280]
//   d_in[2] = Param_b  float32 [16]
//   d_in[3] = w_rows   int32   [E]      E = 16777216
//   d_in[4] = w_cols   int32   [E]
//   d_in[5] = w_params int32   [E]
//   d_in[6] = b_params int32   [N]
// Output: float32 [N]
//
// Model (R5-R12 evidence): LTS-op-rate bound. ~36M L2 ops = 16.7M REDG
// atomics + ~13M gather misses (x 1MB vs 228KB L1 -> 22% hit) + 6.3M index
// fills, at ~0.75 op/cyc/slice = the observed L2 88%. R13 lever: fp16-
// compress x into 512KB device scratch -> L1 hit ~45%, gather misses -28%,
// total LTS ops -10%. Precision: fp16 RMS rel err 2.8e-4 << 1e-3 (norm).

#define GCD_NPARAMS 1280
#define GCD_NCAP    262144

// fp16 copy of x (512 KB). Static device scratch (no allocs allowed).
__device__ __half g_x16[GCD_NCAP];

// ---------------------------------------------------------------------------
// Kernel 0: compress x -> fp16 scratch. float4 in, 4x half out. ~1 us.
// ---------------------------------------------------------------------------
__global__ __launch_bounds__(256)
void gcd_x_compress(const float4* __restrict__ x4, int n4) {
    int i = blockIdx.x * blockDim.x + threadIdx.x;
    if (i < n4) {
        float4 v = __ldcs(&x4[i]);
        __half2* dst = reinterpret_cast<__half2*>(g_x16) + i * 2;
        dst[0] = __floats2half2_rn(v.x, v.y);
        dst[1] = __floats2half2_rn(v.z, v.w);
    }
}

// Scalar compress tail (N % 4) — defensive.
__global__ __launch_bounds__(128)
void gcd_x_compress_tail(const float* __restrict__ x, int start, int n) {
    int i = start + blockIdx.x * blockDim.x + threadIdx.x;
    if (i < n) g_x16[i] = __float2half_rn(x[i]);
}

// ---------------------------------------------------------------------------
// Kernel 1: out = Param_b[b_params]  (d_out arrives poisoned). Vectorized.
// ---------------------------------------------------------------------------
__global__ __launch_bounds__(256)
void gcd_bias_init(float4* __restrict__ out,
                   const float* __restrict__ Pb,
                   const int4* __restrict__ bp,
                   int n4) {
    __shared__ float sPb[16];
    if (threadIdx.x < 16) sPb[threadIdx.x] = Pb[threadIdx.x];
    __syncthreads();

    int i = blockIdx.x * blockDim.x + threadIdx.x;
    if (i < n4) {
        int4 b = __ldcs(&bp[i]);
        float4 o;
        o.x = sPb[b.x];
        o.y = sPb[b.y];
        o.z = sPb[b.z];
        o.w = sPb[b.w];
        out[i] = o;
    }
}

__global__ __launch_bounds__(128)
void gcd_bias_tail(float* __restrict__ out,
                   const float* __restrict__ Pb,
                   const int* __restrict__ bp,
                   int start, int n) {
    int i = start + blockIdx.x * blockDim.x + threadIdx.x;
    if (i < n) out[i] = __ldg(&Pb[__ldg(&bp[i])]);
}

// ---------------------------------------------------------------------------
// Kernel 2 (fp16-x path): edge scatter, 4 edges/thread (measured-best shape).
//  - index streams via __ldcs (evict-first, coalesced LDG.128)
//  - x gathered as fp16 from 512KB scratch (L1 hit ~45% vs 22% for fp32)
//  - Param_W staged in smem; product in fp32; atomicAdd -> REDG
// ---------------------------------------------------------------------------
__global__ __launch_bounds__(256)
void gcd_edge_scatter_h(const float* __restrict__ Pw,
                        const int4* __restrict__ rows,
                        const int4* __restrict__ cols,
                        const int4* __restrict__ params,
                        float* __restrict__ out,
                        int e4) {
    __shared__ float sPw[GCD_NPARAMS];
    for (int i = threadIdx.x; i < GCD_NPARAMS; i += blockDim.x)
        sPw[i] = Pw[i];
    __syncthreads();

    int i = blockIdx.x * blockDim.x + threadIdx.x;
    if (i >= e4) return;

    int4 c = __ldcs(&cols[i]);
    int4 p = __ldcs(&params[i]);
    int4 r = __ldcs(&rows[i]);

    // 4 independent fp16 gathers (latency overlapped).
    __half ha = __ldg(&g_x16[c.x]);
    __half hb = __ldg(&g_x16[c.y]);
    __half hc = __ldg(&g_x16[c.z]);
    __half hd = __ldg(&g_x16[c.w]);

    float v0 = sPw[p.x] * __half2float(ha);
    float v1 = sPw[p.y] * __half2float(hb);
    float v2 = sPw[p.z] * __half2float(hc);
    float v3 = sPw[p.w] * __half2float(hd);

    atomicAdd(&out[r.x], v0);
    atomicAdd(&out[r.y], v1);
    atomicAdd(&out[r.z], v2);
    atomicAdd(&out[r.w], v3);
}

// fp32 fallback path (used if N exceeds the scratch capacity).
__global__ __launch_bounds__(256)
void gcd_edge_scatter_f(const float* __restrict__ x,
                        const float* __restrict__ Pw,
                        const int4* __restrict__ rows,
                        const int4* __restrict__ cols,
                        const int4* __restrict__ params,
                        float* __restrict__ out,
                        int e4) {
    __shared__ float sPw[GCD_NPARAMS];
    for (int i = threadIdx.x; i < GCD_NPARAMS; i += blockDim.x)
        sPw[i] = Pw[i];
    __syncthreads();

    int i = blockIdx.x * blockDim.x + threadIdx.x;
    if (i >= e4) return;

    int4 c = __ldcs(&cols[i]);
    int4 p = __ldcs(&params[i]);
    int4 r = __ldcs(&rows[i]);

    float xa = __ldg(&x[c.x]);
    float xb = __ldg(&x[c.y]);
    float xc = __ldg(&x[c.z]);
    float xd = __ldg(&x[c.w]);

    atomicAdd(&out[r.x], sPw[p.x] * xa);
    atomicAdd(&out[r.y], sPw[p.y] * xb);
    atomicAdd(&out[r.z], sPw[p.z] * xc);
    atomicAdd(&out[r.w], sPw[p.w] * xd);
}

// Scalar edge tail (E % 4) — defensive; uses fp32 x (exact), E = 2^24 so unused.
__global__ __launch_bounds__(128)
void gcd_edge_tail(const float* __restrict__ x,
                   const float* __restrict__ Pw,
                   const int* __restrict__ rows,
                   const int* __restrict__ cols,
                   const int* __restrict__ params,
                   float* __restrict__ out,
                   int start, int E) {
    int e = start + blockIdx.x * blockDim.x + threadIdx.x;
    if (e < E) {
        float v = __ldg(&Pw[__ldg(&params[e])]) * __ldg(&x[__ldg(&cols[e])]);
        atomicAdd(&out[__ldg(&rows[e])], v);
    }
}

extern "C" void kernel_launch(void* const* d_in, const int* in_sizes, int n_in,
                              void* d_out, int out_size) {
    const float* x   = (const float*)d_in[0];
    const float* Pw  = (const float*)d_in[1];
    const float* Pb  = (const float*)d_in[2];
    const int* rows  = (const int*)d_in[3];
    const int* cols  = (const int*)d_in[4];
    const int* prm   = (const int*)d_in[5];
    const int* bp    = (const int*)d_in[6];
    float* out       = (float*)d_out;

    const int N  = out_size;
    const int Nx = in_sizes[0];
    const int E  = in_sizes[3];

    const bool use_h = (Nx <= GCD_NCAP);

    // 0) compress x -> fp16 scratch (runs every replay; deterministic)
    if (use_h) {
        const int x4 = Nx >> 2;
        if (x4 > 0)
            gcd_x_compress<<<(x4 + 255) / 256, 256>>>((const float4*)x, x4);
        const int xts = x4 << 2;
        if (xts < Nx)
            gcd_x_compress_tail<<<((Nx - xts) + 127) / 128, 128>>>(x, xts, Nx);
    }

    // 1) out = Param_b[b_params]  (also clears the 0xAA poison)
    const int n4 = N >> 2;
    if (n4 > 0) {
        gcd_bias_init<<<(n4 + 255) / 256, 256>>>(
            (float4*)out, Pb, (const int4*)bp, n4);
    }
    const int btail_start = n4 << 2;
    if (btail_start < N) {
        gcd_bias_tail<<<((N - btail_start) + 127) / 128, 128>>>(
            out, Pb, bp, btail_start, N);
    }

    // 2) scatter-accumulate the edges, 4 per thread
    const int e4 = E >> 2;
    if (e4 > 0) {
        if (use_h) {
            gcd_edge_scatter_h<<<(e4 + 255) / 256, 256>>>(
                Pw, (const int4*)rows, (const int4*)cols, (const int4*)prm,
                out, e4);
        } else {
            gcd_edge_scatter_f<<<(e4 + 255) / 256, 256>>>(
                x, Pw, (const int4*)rows, (const int4*)cols, (const int4*)prm,
                out, e4);
        }
    }
    const int tail_start = e4 << 2;
    const int tail = E - tail_start;
    if (tail > 0) {
        gcd_edge_tail<<<(tail + 127) / 128, 128>>>(
            x, Pw, rows, cols, prm, out, tail_start, E);
    }
}

// round 14
// speedup vs baseline: 1.0410x; 1.0410x over previous
#include <cuda_runtime.h>
#include <cuda_bf16.h>

// GraphConvDistanceLayer: out[i] = sum_{e: rows[e]==i} Param_W[params[e]] * x[cols[e]]
//                                 + Param_b[b_params[i]]
//
// Inputs (metadata order):
//   d_in[0] = x        float32 [N]      N = 262144
//   d_in[1] = Param_W  float32 [1280]
//   d_in[2] = Param_b  float32 [16]
//   d_in[3] = w_rows   int32   [E]      E = 16777216
//   d_in[4] = w_cols   int32   [E]
//   d_in[5] = w_params int32   [E]
//   d_in[6] = b_params int32   [N]
// Output: float32 [N]
//
// Model (R5-R13 evidence): per-SM LSU/L1tex wavefront-rate bound. Each edge
// costs 1 divergent gather wavefront + 1 atomic lane, hit or miss — E+E =
// 33.5M ops / 148 SM ~= 113us hard floor; edge kernel measures 131.6us.
// Caching (fp16/-ldcs/carveout) and MLP all proven neutral. R14: revert
// fp16; reclaim the ~4.3us periphery by replacing the serialized bias-init
// kernel with memset(0) + bias-as-atomics fused into the edge kernel
// (all writes atomic -> no cross-block ordering hazard, one kernel node).

#define GCD_NPARAMS 1280

// ---------------------------------------------------------------------------
// Fused kernel: item space = [0, e4) edge-quads, [e4, e4+n4) bias-quads,
// [e4+n4, e4+n4+ntail) scalar bias tail. out must be pre-zeroed (memset node).
//  - edge-quad: 3x coalesced LDG.128 index loads (__ldcs, evict-first),
//    4 divergent x-gathers, Param_W from smem, 4 REDG atomics
//  - bias-quad: 1x LDG.128 of b_params, Pb via __ldg (16 floats, L1-resident),
//    4 REDG atomics
// ---------------------------------------------------------------------------
__global__ __launch_bounds__(256)
void gcd_fused(const float* __restrict__ x,
               const float* __restrict__ Pw,
               const float* __restrict__ Pb,
               const int4* __restrict__ rows,
               const int4* __restrict__ cols,
               const int4* __restrict__ params,
               const int* __restrict__ bp,
               float* __restrict__ out,
               int e4, int n4, int ntail, int N) {
    __shared__ float sPw[GCD_NPARAMS];
    for (int i = threadIdx.x; i < GCD_NPARAMS; i += blockDim.x)
        sPw[i] = Pw[i];
    __syncthreads();

    int i = blockIdx.x * blockDim.x + threadIdx.x;

    if (i < e4) {
        // ---- edge quad ----
        int4 c = __ldcs(&cols[i]);
        int4 p = __ldcs(&params[i]);
        int4 r = __ldcs(&rows[i]);

        // 4 independent x-gathers (latency overlapped).
        float xa = __ldg(&x[c.x]);
        float xb = __ldg(&x[c.y]);
        float xc = __ldg(&x[c.z]);
        float xd = __ldg(&x[c.w]);

        float v0 = sPw[p.x] * xa;
        float v1 = sPw[p.y] * xb;
        float v2 = sPw[p.z] * xc;
        float v3 = sPw[p.w] * xd;

        atomicAdd(&out[r.x], v0);
        atomicAdd(&out[r.y], v1);
        atomicAdd(&out[r.z], v2);
        atomicAdd(&out[r.w], v3);
    } else if (i < e4 + n4) {
        // ---- bias quad ----
        int j = i - e4;                       // quad index into b_params
        int4 b = __ldcs(&((const int4*)bp)[j]);
        int o = j * 4;
        atomicAdd(&out[o + 0], __ldg(&Pb[b.x]));
        atomicAdd(&out[o + 1], __ldg(&Pb[b.y]));
        atomicAdd(&out[o + 2], __ldg(&Pb[b.z]));
        atomicAdd(&out[o + 3], __ldg(&Pb[b.w]));
    } else if (i < e4 + n4 + ntail) {
        // ---- scalar bias tail (N % 4) ----
        int o = n4 * 4 + (i - e4 - n4);
        if (o < N)
            atomicAdd(&out[o], __ldg(&Pb[__ldg(&bp[o])]));
    }
}

// Scalar edge tail (E % 4 != 0) — defensive; E = 2^24 so normally unused.
// out is zero-initialized and all writes atomic, so this can run after the
// fused kernel with no hazard.
__global__ __launch_bounds__(128)
void gcd_edge_tail(const float* __restrict__ x,
                   const float* __restrict__ Pw,
                   const int* __restrict__ rows,
                   const int* __restrict__ cols,
                   const int* __restrict__ params,
                   float* __restrict__ out,
                   int start, int E) {
    int e = start + blockIdx.x * blockDim.x + threadIdx.x;
    if (e < E) {
        float v = __ldg(&Pw[__ldg(&params[e])]) * __ldg(&x[__ldg(&cols[e])]);
        atomicAdd(&out[__ldg(&rows[e])], v);
    }
}

extern "C" void kernel_launch(void* const* d_in, const int* in_sizes, int n_in,
                              void* d_out, int out_size) {
    const float* x   = (const float*)d_in[0];
    const float* Pw  = (const float*)d_in[1];
    const float* Pb  = (const float*)d_in[2];
    const int* rows  = (const int*)d_in[3];
    const int* cols  = (const int*)d_in[4];
    const int* prm   = (const int*)d_in[5];
    const int* bp    = (const int*)d_in[6];
    float* out       = (float*)d_out;

    const int N = out_size;
    const int E = in_sizes[3];

    // 0) zero out (clears the 0xAA poison; capture-legal memset node)
    cudaMemsetAsync(out, 0, (size_t)N * sizeof(float), 0);

    // 1) fused edges + bias, all-atomic accumulation
    const int e4 = E >> 2;
    const int n4 = N >> 2;
    const int ntail = N - (n4 << 2);
    const int total = e4 + n4 + ntail;
    if (total > 0) {
        gcd_fused<<<(total + 255) / 256, 256>>>(
            x, Pw, Pb,
            (const int4*)rows, (const int4*)cols, (const int4*)prm,
            bp, out, e4, n4, ntail, N);
    }

    // 2) defensive scalar edge tail (E % 4 != 0; unused for E = 2^24)
    const int tail_start = e4 << 2;
    const int tail = E - tail_start;
    if (tail > 0) {
        gcd_edge_tail<<<(tail + 127) / 128, 128>>>(
            x, Pw, rows, cols, prm, out, tail_start, E);
    }
}